// round 12
// baseline (speedup 1.0000x reference)
#include <cuda_runtime.h>
#include <math.h>

#define NB 128
#define D_IMG 8192
#define D_LANG 4096
#define NCH 64            // chunks per matrix: img KC=128, lang KC=64
#define GRID 128          // 64 img + 64 lang blocks, all co-resident
#define NT 256
#define SMEM_TOTAL (128 * 132 * 4)   // Ts[128][KC+4] fp32, img worst case

// ---------- scratch (static device memory; no allocations) ----------
__device__ float d_part_img[NCH * NB * NB];
__device__ float d_part_lang[NCH * NB * NB];
__device__ float d_diag[2][NCH][NB];
__device__ float d_pre[2 * NB * NB];
__device__ float d_lse[2 * NB];
__device__ unsigned g_count[2];
__device__ volatile unsigned g_phase[2];

__device__ __forceinline__ void tf32_split(float x, unsigned& hi, unsigned& lo) {
    asm("cvt.rna.tf32.f32 %0, %1;" : "=r"(hi) : "f"(x));
    float r = x - __uint_as_float(hi);
    asm("cvt.rna.tf32.f32 %0, %1;" : "=r"(lo) : "f"(r));
}

#define MMA(C, A, B0, B1)                                                     \
    asm volatile("mma.sync.aligned.m16n8k8.row.col.f32.tf32.tf32.f32 "        \
                 "{%0,%1,%2,%3}, {%4,%5,%6,%7}, {%8,%9}, {%0,%1,%2,%3};"      \
                 : "+f"(C[0]), "+f"(C[1]), "+f"(C[2]), "+f"(C[3])             \
                 : "r"(A[0]), "r"(A[1]), "r"(A[2]), "r"(A[3]),                 \
                   "r"(B0), "r"(B1))

// sense-reversing grid barrier; all GRID blocks are co-resident
__device__ __forceinline__ void grid_bar(int id) {
    __syncthreads();
    if (threadIdx.x == 0) {
        __threadfence();
        unsigned p = g_phase[id];
        unsigned old = atomicAdd(&g_count[id], 1);
        if (old == GRID - 1) {
            g_count[id] = 0;
            __threadfence();
            g_phase[id] = p + 1;
        } else {
            while (g_phase[id] == p) {}
        }
        __threadfence();
    }
    __syncthreads();
}

// one full symmetric 128x128 Gram tile for k-chunk [k0, k0+KCc) via tf32 mma
template <int KCc>
__device__ __forceinline__ void gram_tile(const float* __restrict__ F, int D,
                                          int k0, float* __restrict__ part,
                                          float* __restrict__ diag_out,
                                          float* Ts, int t) {
    constexpr int S = KCc + 4;            // padded stride: banks (4r+c)%32, bijective
    constexpr int QPR = KCc / 4;          // float4 quads per row
    constexpr int QPT = NB * QPR / NT;    // quads per thread
    constexpr int QSH = (KCc == 128) ? 5 : 4;

    {   // stage fp32 tile
        const float4* Fp = (const float4*)F;
        int D4 = D >> 2, kq0 = k0 >> 2;
#pragma unroll
        for (int l = 0; l < QPT; l++) {
            int qi = t + NT * l;
            int row = qi >> QSH, q = qi & (QPR - 1);
            float4 v = Fp[(size_t)row * D4 + kq0 + q];
            *(float4*)&Ts[row * S + 4 * q] = v;
        }
    }
    __syncthreads();

    int wid = t >> 5, lane = t & 31;
    int wm = wid & 3, wn = wid >> 2;      // warp tile: rows [32*wm,+32), cols [64*wn,+64)
    int grp = lane >> 2, tig = lane & 3;

    float c[2][8][4];
#pragma unroll
    for (int mt = 0; mt < 2; mt++)
#pragma unroll
        for (int nt = 0; nt < 8; nt++)
#pragma unroll
            for (int e = 0; e < 4; e++) c[mt][nt][e] = 0.f;

#pragma unroll 1
    for (int ks = 0; ks < KCc / 8; ks++) {
        int kk = ks * 8;
        unsigned ahi[2][4], alo[2][4];
#pragma unroll
        for (int mt = 0; mt < 2; mt++) {
            int r0 = wm * 32 + mt * 16 + grp;
            tf32_split(Ts[r0 * S + kk + tig],           ahi[mt][0], alo[mt][0]);
            tf32_split(Ts[(r0 + 8) * S + kk + tig],     ahi[mt][1], alo[mt][1]);
            tf32_split(Ts[r0 * S + kk + tig + 4],       ahi[mt][2], alo[mt][2]);
            tf32_split(Ts[(r0 + 8) * S + kk + tig + 4], ahi[mt][3], alo[mt][3]);
        }
#pragma unroll
        for (int nt = 0; nt < 8; nt++) {
            int nr = wn * 64 + nt * 8 + grp;
            unsigned bh0, bl0, bh1, bl1;
            tf32_split(Ts[nr * S + kk + tig],     bh0, bl0);
            tf32_split(Ts[nr * S + kk + tig + 4], bh1, bl1);
#pragma unroll
            for (int mt = 0; mt < 2; mt++) {
                MMA(c[mt][nt], ahi[mt], bh0, bh1);   // hi*hi
                MMA(c[mt][nt], ahi[mt], bl0, bl1);   // hi*lo
                MMA(c[mt][nt], alo[mt], bh0, bh1);   // lo*hi
            }
        }
    }

    // epilogue: write tile + extract diagonal
#pragma unroll
    for (int mt = 0; mt < 2; mt++)
#pragma unroll
        for (int nt = 0; nt < 8; nt++) {
            int row = wm * 32 + mt * 16 + grp;
            int col = wn * 64 + nt * 8 + 2 * tig;
            *(float2*)&part[row * NB + col] =
                make_float2(c[mt][nt][0], c[mt][nt][1]);
            *(float2*)&part[(row + 8) * NB + col] =
                make_float2(c[mt][nt][2], c[mt][nt][3]);
            if (col == row)          diag_out[row] = c[mt][nt][0];
            else if (col + 1 == row) diag_out[row] = c[mt][nt][1];
            if (col == row + 8)          diag_out[row + 8] = c[mt][nt][2];
            else if (col + 1 == row + 8) diag_out[row + 8] = c[mt][nt][3];
        }
}

__global__ __launch_bounds__(NT, 1)
void k_fused(const float* __restrict__ img, const float* __restrict__ lang,
             const float* __restrict__ temp, float* __restrict__ out) {
    extern __shared__ float Ts[];
    int bid = blockIdx.x;
    int t = threadIdx.x;

    // ================= PHASE 1: Gram partial via tf32 mma.sync ==============
    {
        int m = bid >> 6;            // 0 = image, 1 = lang
        int ch = bid & 63;
        if (m == 0)
            gram_tile<128>(img, D_IMG, ch * 128,
                           d_part_img + ch * NB * NB, &d_diag[0][ch][0], Ts, t);
        else
            gram_tile<64>(lang, D_LANG, ch * 64,
                          d_part_lang + ch * NB * NB, &d_diag[1][ch][0], Ts, t);
    }

    grid_bar(0);

    // ================= PHASE 2: norms + pre + row lse =================
    float* norm0 = Ts;           // [128] image norms
    float* norm1 = Ts + 128;     // [128] lang norms
    float* sred  = Ts + 256;     // [8] per-warp partials
    {
        int mm = t >> 7, j = t & 127;
        float s = 0.f;
#pragma unroll 16
        for (int ci = 0; ci < NCH; ci++) s += d_diag[mm][ci][j];   // coalesced
        (mm ? norm1 : norm0)[j] = s;
    }
    float expT = __expf(temp[0]);
    __syncthreads();

    {
        int half = t >> 7, j = t & 127;
        int r = half ? bid + GRID : bid;     // rows 0-127 and 128-255, exact
        int m = r >> 7, i = r & 127;
        const float* part = m ? d_part_lang : d_part_img;
        float g = 0.f;
#pragma unroll 16
        for (int ci = 0; ci < NCH; ci++) g += part[ci * NB * NB + i * NB + j];
        const float* nrm = m ? norm1 : norm0;
        float sq = nrm[i] + nrm[j] - 2.f * g;
        float pre = (j == i) ? 0.f : -sqrtf(fmaxf(sq, 0.f)) * expT;
        d_pre[m * NB * NB + i * NB + j] = pre;
        float e = __expf(pre);
#pragma unroll
        for (int o = 16; o; o >>= 1) e += __shfl_xor_sync(~0u, e, o);
        if ((j & 31) == 0) sred[t >> 5] = e;
        __syncthreads();
        if (j == 0) {
            int base = half * 4;
            float s = sred[base] + sred[base + 1] + sred[base + 2] + sred[base + 3];
            d_lse[r] = __logf(s);
        }
    }

    grid_bar(1);

    // ================= PHASE 3: KL combine + column sum =================
    if (t < NB) {
        int i = t;
        float af = d_pre[i * NB + bid] - d_lse[i];
        float ag = d_pre[NB * NB + i * NB + bid] - d_lse[NB + i];
        float v = __expf(ag) * (ag - af);
#pragma unroll
        for (int o = 16; o; o >>= 1) v += __shfl_xor_sync(~0u, v, o);
        if ((i & 31) == 0) sred[i >> 5] = v;
    }
    __syncthreads();
    if (t == 0)
        out[bid] = sred[0] + sred[1] + sred[2] + sred[3];
}

extern "C" void kernel_launch(void* const* d_in, const int* in_sizes, int n_in,
                              void* d_out, int out_size) {
    const float* img = (const float*)d_in[0];
    const float* lang = (const float*)d_in[1];
    const float* temp = (const float*)d_in[2];
    float* out = (float*)d_out;
    (void)in_sizes; (void)n_in; (void)out_size;

    cudaFuncSetAttribute(k_fused, cudaFuncAttributeMaxDynamicSharedMemorySize,
                         (int)SMEM_TOTAL);
    k_fused<<<GRID, NT, SMEM_TOTAL>>>(img, lang, temp, out);
}

// round 16
// speedup vs baseline: 1.3551x; 1.3551x over previous
#include <cuda_runtime.h>
#include <math.h>

#define NB 128
#define D_IMG 8192
#define D_LANG 4096
#define NCH 64            // chunks per matrix: img KC=128, lang KC=64
#define GRID 128          // 64 img + 64 lang blocks, all co-resident
#define NT 256
// smem: two packed-bf16 tiles [128][stride=68 words] (img case)
#define SMEM_TOTAL (2 * 128 * 68 * 4)

// ---------- scratch (static device memory; no allocations) ----------
__device__ float d_part_img[NCH * NB * NB];
__device__ float d_part_lang[NCH * NB * NB];
__device__ float d_diag[2][NCH][NB];
__device__ float d_pre[2 * NB * NB];
__device__ float d_lse[2 * NB];
__device__ unsigned g_count[2];
__device__ volatile unsigned g_phase[2];

// pack two floats into bf16x2 (x -> low half, y -> high half)
__device__ __forceinline__ unsigned pack_bf16(float x, float y) {
    unsigned w;
    asm("cvt.rn.bf16x2.f32 %0, %1, %2;" : "=r"(w) : "f"(y), "f"(x));
    return w;
}

#define MMAB(C, A, B0, B1)                                                    \
    asm volatile("mma.sync.aligned.m16n8k16.row.col.f32.bf16.bf16.f32 "       \
                 "{%0,%1,%2,%3}, {%4,%5,%6,%7}, {%8,%9}, {%0,%1,%2,%3};"      \
                 : "+f"(C[0]), "+f"(C[1]), "+f"(C[2]), "+f"(C[3])             \
                 : "r"(A[0]), "r"(A[1]), "r"(A[2]), "r"(A[3]),                 \
                   "r"(B0), "r"(B1))

// sense-reversing grid barrier; all GRID blocks are co-resident
__device__ __forceinline__ void grid_bar(int id) {
    __syncthreads();
    if (threadIdx.x == 0) {
        __threadfence();
        unsigned p = g_phase[id];
        unsigned old = atomicAdd(&g_count[id], 1);
        if (old == GRID - 1) {
            g_count[id] = 0;
            __threadfence();
            g_phase[id] = p + 1;
        } else {
            while (g_phase[id] == p) {}
        }
        __threadfence();
    }
    __syncthreads();
}

// full symmetric 128x128 Gram tile for k-chunk [k0,k0+KCc) via bf16-split mma
template <int KCc>
__device__ __forceinline__ void gram_tile(const float* __restrict__ F, int D,
                                          int k0, float* __restrict__ part,
                                          float* __restrict__ diag_out,
                                          unsigned* Hs, int t) {
    constexpr int S = KCc / 2 + 4;        // word stride; S%32==4 -> conflict-free
    constexpr int QPR = KCc / 4;          // float4 quads per row
    constexpr int QPT = NB * QPR / NT;
    constexpr int QSH = (KCc == 128) ? 5 : 4;
    unsigned* Ls = Hs + NB * S;

    {   // stage: load fp32, split into packed-bf16 hi/lo tiles (one CVT per elem)
        const float4* Fp = (const float4*)F;
        int D4 = D >> 2, kq0 = k0 >> 2;
#pragma unroll
        for (int l = 0; l < QPT; l++) {
            int qi = t + NT * l;
            int row = qi >> QSH, q = qi & (QPR - 1);
            float4 v = Fp[(size_t)row * D4 + kq0 + q];
            unsigned h0 = pack_bf16(v.x, v.y);
            unsigned h1 = pack_bf16(v.z, v.w);
            float lx = v.x - __uint_as_float(h0 << 16);
            float ly = v.y - __uint_as_float(h0 & 0xFFFF0000u);
            float lz = v.z - __uint_as_float(h1 << 16);
            float lw = v.w - __uint_as_float(h1 & 0xFFFF0000u);
            unsigned l0 = pack_bf16(lx, ly);
            unsigned l1 = pack_bf16(lz, lw);
            *(uint2*)&Hs[row * S + 2 * q] = make_uint2(h0, h1);
            *(uint2*)&Ls[row * S + 2 * q] = make_uint2(l0, l1);
        }
    }
    __syncthreads();

    int wid = t >> 5, lane = t & 31;
    int wm = wid & 3, wn = wid >> 2;      // warp tile: rows [32wm,+32), cols [64wn,+64)
    int grp = lane >> 2, tig = lane & 3;

    float c[2][8][4];
#pragma unroll
    for (int mt = 0; mt < 2; mt++)
#pragma unroll
        for (int nt = 0; nt < 8; nt++)
#pragma unroll
            for (int e = 0; e < 4; e++) c[mt][nt][e] = 0.f;

#pragma unroll
    for (int ks = 0; ks < KCc / 16; ks++) {
        int kb = ks * 8;                   // 8 k-pairs per k16 step
        unsigned ah[2][4], al[2][4];
#pragma unroll
        for (int mt = 0; mt < 2; mt++) {
            int r0 = wm * 32 + mt * 16 + grp;
            ah[mt][0] = Hs[r0 * S + kb + tig];
            ah[mt][1] = Hs[(r0 + 8) * S + kb + tig];
            ah[mt][2] = Hs[r0 * S + kb + tig + 4];
            ah[mt][3] = Hs[(r0 + 8) * S + kb + tig + 4];
            al[mt][0] = Ls[r0 * S + kb + tig];
            al[mt][1] = Ls[(r0 + 8) * S + kb + tig];
            al[mt][2] = Ls[r0 * S + kb + tig + 4];
            al[mt][3] = Ls[(r0 + 8) * S + kb + tig + 4];
        }
#pragma unroll
        for (int nt = 0; nt < 8; nt++) {
            int nr = wn * 64 + nt * 8 + grp;
            unsigned bh0 = Hs[nr * S + kb + tig];
            unsigned bh1 = Hs[nr * S + kb + tig + 4];
            unsigned bl0 = Ls[nr * S + kb + tig];
            unsigned bl1 = Ls[nr * S + kb + tig + 4];
#pragma unroll
            for (int mt = 0; mt < 2; mt++) {
                MMAB(c[mt][nt], ah[mt], bh0, bh1);   // hi*hi
                MMAB(c[mt][nt], ah[mt], bl0, bl1);   // hi*lo
                MMAB(c[mt][nt], al[mt], bh0, bh1);   // lo*hi
            }
        }
    }

    // epilogue: write tile + extract diagonal
    // c0=(r,2tig) c1=(r,2tig+1) c2=(r+8,2tig) c3=(r+8,2tig+1)
#pragma unroll
    for (int mt = 0; mt < 2; mt++)
#pragma unroll
        for (int nt = 0; nt < 8; nt++) {
            int row = wm * 32 + mt * 16 + grp;
            int col = wn * 64 + nt * 8 + 2 * tig;
            *(float2*)&part[row * NB + col] =
                make_float2(c[mt][nt][0], c[mt][nt][1]);
            *(float2*)&part[(row + 8) * NB + col] =
                make_float2(c[mt][nt][2], c[mt][nt][3]);
            if (col == row)          diag_out[row] = c[mt][nt][0];
            else if (col + 1 == row) diag_out[row] = c[mt][nt][1];
            if (col == row + 8)          diag_out[row + 8] = c[mt][nt][2];
            else if (col + 1 == row + 8) diag_out[row + 8] = c[mt][nt][3];
        }
}

__global__ __launch_bounds__(NT, 1)
void k_fused(const float* __restrict__ img, const float* __restrict__ lang,
             const float* __restrict__ temp, float* __restrict__ out) {
    extern __shared__ float Ts[];
    int bid = blockIdx.x;
    int t = threadIdx.x;

    // ================= PHASE 1: Gram partial via bf16-split mma.sync ========
    {
        int m = bid >> 6;            // 0 = image, 1 = lang
        int ch = bid & 63;
        if (m == 0)
            gram_tile<128>(img, D_IMG, ch * 128,
                           d_part_img + ch * NB * NB, &d_diag[0][ch][0],
                           (unsigned*)Ts, t);
        else
            gram_tile<64>(lang, D_LANG, ch * 64,
                          d_part_lang + ch * NB * NB, &d_diag[1][ch][0],
                          (unsigned*)Ts, t);
    }

    grid_bar(0);

    // ================= PHASE 2: norms + pre + row lse =================
    float* norm0 = Ts;           // [128] image norms
    float* norm1 = Ts + 128;     // [128] lang norms
    float* sred  = Ts + 256;     // [8] per-warp partials
    {
        int mm = t >> 7, j = t & 127;
        float s = 0.f;
#pragma unroll 16
        for (int ci = 0; ci < NCH; ci++) s += d_diag[mm][ci][j];   // coalesced
        (mm ? norm1 : norm0)[j] = s;
    }
    float expT = __expf(temp[0]);
    __syncthreads();

    {
        int half = t >> 7, j = t & 127;
        int r = half ? bid + GRID : bid;     // rows 0-127 and 128-255, exact
        int m = r >> 7, i = r & 127;
        const float* part = m ? d_part_lang : d_part_img;
        float g = 0.f;
#pragma unroll 16
        for (int ci = 0; ci < NCH; ci++) g += part[ci * NB * NB + i * NB + j];
        const float* nrm = m ? norm1 : norm0;
        float sq = nrm[i] + nrm[j] - 2.f * g;
        float pre = (j == i) ? 0.f : -sqrtf(fmaxf(sq, 0.f)) * expT;
        d_pre[m * NB * NB + i * NB + j] = pre;
        float e = __expf(pre);
#pragma unroll
        for (int o = 16; o; o >>= 1) e += __shfl_xor_sync(~0u, e, o);
        if ((j & 31) == 0) sred[t >> 5] = e;
        __syncthreads();
        if (j == 0) {
            int base = half * 4;
            float s = sred[base] + sred[base + 1] + sred[base + 2] + sred[base + 3];
            d_lse[r] = __logf(s);
        }
    }

    grid_bar(1);

    // ================= PHASE 3: KL combine + column sum =================
    if (t < NB) {
        int i = t;
        float af = d_pre[i * NB + bid] - d_lse[i];
        float ag = d_pre[NB * NB + i * NB + bid] - d_lse[NB + i];
        float v = __expf(ag) * (ag - af);
#pragma unroll
        for (int o = 16; o; o >>= 1) v += __shfl_xor_sync(~0u, v, o);
        if ((i & 31) == 0) sred[i >> 5] = v;
    }
    __syncthreads();
    if (t == 0)
        out[bid] = sred[0] + sred[1] + sred[2] + sred[3];
}

extern "C" void kernel_launch(void* const* d_in, const int* in_sizes, int n_in,
                              void* d_out, int out_size) {
    const float* img = (const float*)d_in[0];
    const float* lang = (const float*)d_in[1];
    const float* temp = (const float*)d_in[2];
    float* out = (float*)d_out;
    (void)in_sizes; (void)n_in; (void)out_size;

    cudaFuncSetAttribute(k_fused, cudaFuncAttributeMaxDynamicSharedMemorySize,
                         (int)SMEM_TOTAL);
    k_fused<<<GRID, NT, SMEM_TOTAL>>>(img, lang, temp, out);
}